// round 8
// baseline (speedup 1.0000x reference)
#include <cuda_runtime.h>
#include <cuda_fp16.h>
#include <cstdint>

// ---------------------------------------------------------------------------
// FeatureQuantizerEMA — VQ-VAE EMA quantizer
// Round 5: single fp16 HMMA GEMM + top-2 + exact fp64 rescue (fixed writeback
// grid: 8192 CTAs, one per (b,d) plane, 4-chunk loop).
// outputs concatenated f32: out(33554432), loss(1), embed_idx(131072),
//   new_embed(262144), new_cluster_size(1024), new_ema_embed(262144)
// ---------------------------------------------------------------------------

#define NROWS   131072
#define KEMB    1024
#define DEMB    256
#define HWSZ    4096

#define LOSS_OFF 33554432
#define IDX_OFF  33554433
#define EMB_OFF  33685505
#define CS_OFF   33947649
#define EMA_OFF  33948673
#define FULL_OUT 34210817

#define RESCUE_W 0.06f

// scratch
__device__ __align__(16) int     g_idx[NROWS];
__device__ float   g_count[KEMB];
__device__ float   g_dw[DEMB * KEMB];
__device__ float   g_e2h[KEMB];
__device__ float   g_smooth[KEMB];
__device__ double  g_lossPart[256];
__device__ float   g_spill[262144];
__device__ __align__(16) __half  g_Ehf[KEMB * DEMB];  // E^T fp16, codes-major [k][d]
__device__ __align__(16) float   g_Etf[KEMB * DEMB];  // E^T fp32, codes-major [k][d]

__device__ __forceinline__ uint32_t smem_to_u32(const void* p) {
    uint32_t a;
    asm("{ .reg .u64 t; cvta.to.shared.u64 t, %1; cvt.u32.u64 %0, t; }"
        : "=r"(a) : "l"(p));
    return a;
}

#define LDSM4(r0, r1, r2, r3, a) \
    asm volatile("ldmatrix.sync.aligned.m8n8.x4.shared.b16 {%0,%1,%2,%3}, [%4];" \
                 : "=r"(r0), "=r"(r1), "=r"(r2), "=r"(r3) : "r"(a))
#define LDSM4T(r0, r1, r2, r3, a) \
    asm volatile("ldmatrix.sync.aligned.m8n8.x4.trans.shared.b16 {%0,%1,%2,%3}, [%4];" \
                 : "=r"(r0), "=r"(r1), "=r"(r2), "=r"(r3) : "r"(a))

#define MMA16816(c, a0, a1, a2, a3, b0, b1) \
    asm volatile("mma.sync.aligned.m16n8k16.row.col.f32.f16.f16.f32 " \
                 "{%0,%1,%2,%3}, {%4,%5,%6,%7}, {%8,%9}, {%0,%1,%2,%3};" \
                 : "+f"((c)[0]), "+f"((c)[1]), "+f"((c)[2]), "+f"((c)[3]) \
                 : "r"(a0), "r"(a1), "r"(a2), "r"(a3), "r"(b0), "r"(b1))

// ===========================================================================
// prep kernels (argmin stays launch index 3 for the ncu capture slot)
// ===========================================================================
__global__ void prep_zero_kernel() {
    int i = blockIdx.x * blockDim.x + threadIdx.x;
    if (i < DEMB * KEMB) g_dw[i] = 0.0f;
    if (i < KEMB) g_count[i] = 0.0f;
    if (i < 256) g_lossPart[i] = 0.0;
}

__global__ void prep_split_kernel(const float* __restrict__ embed) {
    int i = blockIdx.x * blockDim.x + threadIdx.x;   // 0..262143
    int k = i & (KEMB - 1);
    int d = i >> 10;
    float v = embed[i];                              // embed[d][k]
    g_Ehf[k * DEMB + d] = __float2half_rn(v);
    g_Etf[k * DEMB + d] = v;
}

__global__ void prep_norm_kernel(const float* __restrict__ embed) {
    int i = blockIdx.x * blockDim.x + threadIdx.x;   // 0..1023
    float s = 0.0f;
    #pragma unroll 4
    for (int d = 0; d < DEMB; d++) {
        float e = embed[d * KEMB + i];
        s = fmaf(e, e, s);
    }
    g_e2h[i] = 0.5f * s;
}

// ===========================================================================
// argmin: single fp16 HMMA GEMM + top-2 tracking + exact rescue
//  CTA = 128 rows x 1024 codes, 256 threads (8 warps = 4m x 2n).
// ===========================================================================
#define PA 136                       // A pitch (m) in halfs
#define PB 72                        // B pitch (k) in halfs
#define SM_E2H  0                    // 1024 f32 = 4096 B
#define SM_MST  4096                 // 128 f32 (per-row approx min)
#define SM_CAND 4608                 // 128 u64 (packed winner)
#define SM_A    8192                 // Ah 256*136*2 = 69632
#define SM_ALO  (8192 + 69632)       // Al
#define SM_B    (8192 + 2 * 69632)   // 147456: 2 stages x 18432 (hi only)
#define SM_RED  SM_B                 // alias after GEMM: rS[2][128]
#define SM_TOT  (SM_B + 2 * 18432)   // 184320

__device__ __forceinline__ void loadB(char* smem, int chunk, int tid) {
    const int stage = chunk & 1;
    const int nb = chunk >> 2, kc = chunk & 3;
    #pragma unroll
    for (int j = 0; j < 4; j++) {
        int i = tid + j * 256;           // 0..1023
        int r = i >> 3;                  // code row 0..127
        int c = i & 7;                   // 16B chunk along k
        const __half* src = g_Ehf + ((size_t)(nb * 128 + r) << 8) + kc * 64 + c * 8;
        uint4 v = *(const uint4*)src;
        *(uint4*)(smem + SM_B + stage * 18432 + r * (PB * 2) + c * 16) = v;
    }
}

// exact rescore: double-accumulated dot of row m against code k
__device__ __forceinline__ void rescore(char* smem, unsigned long long* cand,
                                        const float* e2h, int m, int k) {
    const __half* Ah = (const __half*)(smem + SM_A);
    const __half* Al = (const __half*)(smem + SM_ALO);
    const float4* ev = (const float4*)(g_Etf + ((size_t)k << 8));
    double a0 = 0.0, a1 = 0.0, a2 = 0.0, a3 = 0.0;
    #pragma unroll 8
    for (int d4 = 0; d4 < 64; d4++) {
        float4 e4 = __ldg(&ev[d4]);
        int d = d4 * 4;
        float x0 = __half2float(Ah[(d + 0) * PA + m]) + __half2float(Al[(d + 0) * PA + m]);
        float x1 = __half2float(Ah[(d + 1) * PA + m]) + __half2float(Al[(d + 1) * PA + m]);
        float x2 = __half2float(Ah[(d + 2) * PA + m]) + __half2float(Al[(d + 2) * PA + m]);
        float x3 = __half2float(Ah[(d + 3) * PA + m]) + __half2float(Al[(d + 3) * PA + m]);
        a0 += (double)x0 * (double)e4.x;
        a1 += (double)x1 * (double)e4.y;
        a2 += (double)x2 * (double)e4.z;
        a3 += (double)x3 * (double)e4.w;
    }
    float sc = (float)((double)e2h[k] - (a0 + a1 + a2 + a3));
    uint32_t u = __float_as_uint(sc);
    u = (u & 0x80000000u) ? ~u : (u | 0x80000000u);
    unsigned long long key = ((unsigned long long)u << 10) | (unsigned)k;
    atomicMin(&cand[m], key);
}

__global__ __launch_bounds__(256, 1)
void argmin_mma_kernel(const float* __restrict__ x, float* __restrict__ outIdxF) {
    extern __shared__ char smem[];
    const uint32_t sb = smem_to_u32(smem);
    const int tid = threadIdx.x, lane = tid & 31, wid = tid >> 5;
    const int wm = wid & 3, wn = wid >> 2;

    float* e2h = (float*)(smem + SM_E2H);
    float* mst = (float*)(smem + SM_MST);
    unsigned long long* cand = (unsigned long long*)(smem + SM_CAND);
    for (int i = tid; i < KEMB; i += 256) e2h[i] = g_e2h[i];
    if (tid < 128) cand[tid] = 0xFFFFFFFFFFFFFFFFull;

    // stage A (x rows) as fp16 hi/lo, k-major [d][m], pitch PA
    const int n0 = blockIdx.x << 7;
    const float* xb = x + ((size_t)(n0 >> 12) << 20) + (n0 & (HWSZ - 1));
    __half* Ah = (__half*)(smem + SM_A);
    __half* Al = (__half*)(smem + SM_ALO);
    for (int i = tid; i < 32768; i += 256) {
        int d = i >> 7, m = i & 127;
        float v = xb[(size_t)d * HWSZ + m];
        __half h = __float2half_rn(v);
        float r = v - __half2float(h);
        Ah[d * PA + m] = h;
        Al[d * PA + m] = __float2half_rn(r);
    }
    loadB(smem, 0, tid);
    __syncthreads();

    // lane geometry
    const int g = lane >> 2, t = lane & 3;
    const uint32_t a_k = (uint32_t)((lane & 7) + ((lane & 16) ? 8 : 0));
    const uint32_t a_m = (uint32_t)((lane & 8) ? 8 : 0);
    const uint32_t b_n = (uint32_t)((lane & 7) + ((lane & 16) ? 8 : 0));
    const uint32_t b_k = (uint32_t)((lane & 8) ? 8 : 0);

    // top-2 per slot (4 slots: s = mt*2 + rowhalf)
    float bs1[4], bs2[4];
    int   bk1[4], bk2[4];
    #pragma unroll
    for (int s = 0; s < 4; s++) {
        bs1[s] = 3.4e38f; bs2[s] = 3.4e38f; bk1[s] = 0; bk2[s] = 0;
    }

    #pragma unroll 1
    for (int nb = 0; nb < 8; nb++) {
        float c[2][8][4];
        #pragma unroll
        for (int mt = 0; mt < 2; mt++)
            #pragma unroll
            for (int nt = 0; nt < 8; nt++)
                #pragma unroll
                for (int q = 0; q < 4; q++) c[mt][nt][q] = 0.0f;

        #pragma unroll 1
        for (int kc = 0; kc < 4; kc++) {
            const int chunk = nb * 4 + kc;
            if (chunk < 31) loadB(smem, chunk + 1, tid);
            const uint32_t bbase = sb + SM_B + (uint32_t)(chunk & 1) * 18432;

            #pragma unroll
            for (int ks = 0; ks < 4; ks++) {
                const uint32_t kA = (uint32_t)(kc * 64 + ks * 16);
                uint32_t ah[2][4];
                #pragma unroll
                for (int mt = 0; mt < 2; mt++) {
                    uint32_t aaddr = sb + SM_A
                        + ((kA + a_k) * PA + (uint32_t)(wm * 32 + mt * 16) + a_m) * 2;
                    LDSM4T(ah[mt][0], ah[mt][1], ah[mt][2], ah[mt][3], aaddr);
                }
                uint32_t bh[4][4];
                #pragma unroll
                for (int p = 0; p < 4; p++) {
                    uint32_t baddr = bbase
                        + (((uint32_t)(wn * 64 + p * 16) + b_n) * PB
                           + (uint32_t)(ks * 16) + b_k) * 2;
                    LDSM4(bh[p][0], bh[p][1], bh[p][2], bh[p][3], baddr);
                }
                #pragma unroll
                for (int p = 0; p < 4; p++) {
                    #pragma unroll
                    for (int mt = 0; mt < 2; mt++) {
                        MMA16816(c[mt][2 * p],     ah[mt][0], ah[mt][1], ah[mt][2], ah[mt][3], bh[p][0], bh[p][1]);
                        MMA16816(c[mt][2 * p + 1], ah[mt][0], ah[mt][1], ah[mt][2], ah[mt][3], bh[p][2], bh[p][3]);
                    }
                }
            }
            __syncthreads();
        }

        // epilogue: top-2 update, ascending k (strict < keeps first-min)
        #pragma unroll
        for (int mt = 0; mt < 2; mt++) {
            #pragma unroll
            for (int nt = 0; nt < 8; nt++) {
                int n = nb * 128 + wn * 64 + nt * 8 + 2 * t;
                float sA0 = e2h[n]     - c[mt][nt][0];
                float sA1 = e2h[n + 1] - c[mt][nt][1];
                float sB0 = e2h[n]     - c[mt][nt][2];
                float sB1 = e2h[n + 1] - c[mt][nt][3];
                int s = mt * 2;
                if (sA0 < bs1[s]) { bs2[s]=bs1[s]; bk2[s]=bk1[s]; bs1[s]=sA0; bk1[s]=n; }
                else if (sA0 < bs2[s]) { bs2[s]=sA0; bk2[s]=n; }
                if (sA1 < bs1[s]) { bs2[s]=bs1[s]; bk2[s]=bk1[s]; bs1[s]=sA1; bk1[s]=n+1; }
                else if (sA1 < bs2[s]) { bs2[s]=sA1; bk2[s]=n+1; }
                s++;
                if (sB0 < bs1[s]) { bs2[s]=bs1[s]; bk2[s]=bk1[s]; bs1[s]=sB0; bk1[s]=n; }
                else if (sB0 < bs2[s]) { bs2[s]=sB0; bk2[s]=n; }
                if (sB1 < bs1[s]) { bs2[s]=bs1[s]; bk2[s]=bk1[s]; bs1[s]=sB1; bk1[s]=n+1; }
                else if (sB1 < bs2[s]) { bs2[s]=sB1; bk2[s]=n+1; }
            }
        }
    }

    // per-row approximate min m*: reduce bs1 over t-lanes, then over n-halves
    {
        float rs[4];
        #pragma unroll
        for (int s = 0; s < 4; s++) rs[s] = bs1[s];
        #pragma unroll
        for (int s = 0; s < 4; s++) {
            #pragma unroll
            for (int off = 1; off <= 2; off <<= 1)
                rs[s] = fminf(rs[s], __shfl_xor_sync(0xffffffffu, rs[s], off));
        }
        float* rS = (float*)(smem + SM_RED);
        if (t == 0) {
            #pragma unroll
            for (int s = 0; s < 4; s++) {
                int row = wm * 32 + (s >> 1) * 16 + (s & 1) * 8 + g;
                rS[wn * 128 + row] = rs[s];
            }
        }
        __syncthreads();
        if (tid < 128) mst[tid] = fminf(rS[tid], rS[128 + tid]);
        __syncthreads();
    }

    // candidate rescue: rescore any slot entry within W of m*
    #pragma unroll
    for (int s = 0; s < 4; s++) {
        int row = wm * 32 + (s >> 1) * 16 + (s & 1) * 8 + g;
        float thr = mst[row] + RESCUE_W;
        if (bs1[s] <= thr) rescore(smem, cand, e2h, row, bk1[s]);
        if (bs2[s] <= thr) rescore(smem, cand, e2h, row, bk2[s]);
    }
    __syncthreads();

    if (tid < 128) {
        int k = (int)(cand[tid] & 1023u);
        int n = n0 + tid;
        g_idx[n] = k;
        outIdxF[n] = (float)k;
        atomicAdd(&g_count[k], 1.0f);
    }
}

// ===========================================================================
// writeback: out = gather(embed, idx), loss partials, dw scatter
//  grid 8192 CTAs: one per (b, d); embed row cached in smem; 4 chunks of
//  1024 elements each (256 threads x float4).
// ===========================================================================
__global__ __launch_bounds__(256)
void writeback_kernel(const float* __restrict__ x,
                      const float* __restrict__ embed,
                      float* __restrict__ out) {
    __shared__ float erow[KEMB];
    __shared__ float wsum[8];
    const int bid = blockIdx.x;            // 0..8191
    const int b = bid >> 8, d = bid & 255;
    const int tid = threadIdx.x;

    *(float4*)&erow[tid * 4] = *(const float4*)(embed + ((size_t)d << 10) + tid * 4);
    __syncthreads();

    const size_t base = ((size_t)b << 20) + ((size_t)d << 12);
    const int n0 = b << 12;
    float* dwrow = g_dw + ((size_t)d << 10);
    float ls = 0.0f;

    #pragma unroll
    for (int c2 = 0; c2 < 4; c2++) {
        const int hw = c2 * 1024 + tid * 4;
        float4 xv = *(const float4*)(x + base + hw);
        int4   kv = *(const int4*)(g_idx + n0 + hw);
        float q0 = erow[kv.x], q1 = erow[kv.y], q2 = erow[kv.z], q3 = erow[kv.w];
        *(float4*)(out + base + hw) = make_float4(q0, q1, q2, q3);

        float d0 = q0 - xv.x, d1 = q1 - xv.y, d2 = q2 - xv.z, d3 = q3 - xv.w;
        ls += d0 * d0 + d1 * d1 + d2 * d2 + d3 * d3;

        atomicAdd(dwrow + kv.x, xv.x);
        atomicAdd(dwrow + kv.y, xv.y);
        atomicAdd(dwrow + kv.z, xv.z);
        atomicAdd(dwrow + kv.w, xv.w);
    }

    #pragma unroll
    for (int off = 16; off; off >>= 1)
        ls += __shfl_xor_sync(0xffffffffu, ls, off);
    int lane = tid & 31, w = tid >> 5;
    if (lane == 0) wsum[w] = ls;
    __syncthreads();
    if (tid == 0) {
        float bsum = 0.0f;
        #pragma unroll
        for (int i = 0; i < 8; i++) bsum += wsum[i];
        atomicAdd(&g_lossPart[bid & 255], (double)bsum);
    }
}

// ===========================================================================
// cluster-size / smoothing / loss finalize (shuffle-based)
// ===========================================================================
__global__ __launch_bounds__(1024)
void cs_kernel(const float* __restrict__ cs_in,
               float* __restrict__ outCS,
               float* __restrict__ outLoss) {
    __shared__ float wred[32];
    __shared__ double lred[8];
    __shared__ float nsum_s;
    int k = threadIdx.x;
    int lane = k & 31, w = k >> 5;

    float ncs = cs_in[k] * 0.9f + 0.1f * g_count[k];
    outCS[k] = ncs;
    float sum = ncs;
    #pragma unroll
    for (int off = 16; off; off >>= 1)
        sum += __shfl_xor_sync(0xffffffffu, sum, off);
    if (lane == 0) wred[w] = sum;

    if (k < 256) {
        double lp = g_lossPart[k];
        #pragma unroll
        for (int off = 16; off; off >>= 1)
            lp += __shfl_xor_sync(0xffffffffu, lp, off);
        if (lane == 0) lred[w] = lp;
    }
    __syncthreads();
    if (w == 0) {
        float v = wred[lane];
        #pragma unroll
        for (int off = 16; off; off >>= 1)
            v += __shfl_xor_sync(0xffffffffu, v, off);
        if (lane == 0) nsum_s = v;
    }
    __syncthreads();
    float nsum = nsum_s;
    g_smooth[k] = nsum * ((ncs + 1e-5f) / (nsum + ncs * 1e-5f));
    if (k == 0) {
        double ls = lred[0] + lred[1] + lred[2] + lred[3]
                  + lred[4] + lred[5] + lred[6] + lred[7];
        outLoss[0] = (float)(0.25 * ls / 33554432.0);
    }
}

__global__ __launch_bounds__(256)
void emb_kernel(const float* __restrict__ ema_in,
                float* __restrict__ outEmb,
                float* __restrict__ outEma) {
    int i = blockIdx.x * blockDim.x + threadIdx.x;
    int k = i & 1023;
    float nema = ema_in[i] * 0.9f + 0.1f * g_dw[i];
    outEma[i] = nema;
    outEmb[i] = nema / g_smooth[k];
}

// ===========================================================================
extern "C" void kernel_launch(void* const* d_in, const int* in_sizes, int n_in,
                              void* d_out, int out_size) {
    const float* x     = (const float*)d_in[0];
    const float* embed = (const float*)d_in[1];
    const float* cs    = (const float*)d_in[2];
    const float* ema   = (const float*)d_in[3];
    float* out = (float*)d_out;

    float* spill = nullptr;
    cudaGetSymbolAddress((void**)&spill, g_spill);

    const bool full = (out_size >= FULL_OUT);
    float* pIdx  = full ? out + IDX_OFF  : spill;
    float* pLoss = full ? out + LOSS_OFF : spill;
    float* pEmb  = full ? out + EMB_OFF  : spill;
    float* pCS   = full ? out + CS_OFF   : spill;
    float* pEma  = full ? out + EMA_OFF  : spill;

    cudaFuncSetAttribute(argmin_mma_kernel,
                         cudaFuncAttributeMaxDynamicSharedMemorySize, SM_TOT);

    prep_zero_kernel<<<1024, 256>>>();
    prep_split_kernel<<<1024, 256>>>(embed);
    prep_norm_kernel<<<4, 256>>>(embed);
    argmin_mma_kernel<<<NROWS / 128, 256, SM_TOT>>>(x, pIdx);   // index 3
    writeback_kernel<<<8192, 256>>>(x, embed, out);
    cs_kernel<<<1, 1024>>>(cs, pCS, pLoss);
    emb_kernel<<<1024, 256>>>(ema, pEmb, pEma);
}

// round 10
// speedup vs baseline: 1.3947x; 1.3947x over previous
#include <cuda_runtime.h>
#include <cuda_fp16.h>
#include <cstdint>

// ---------------------------------------------------------------------------
// FeatureQuantizerEMA — VQ-VAE EMA quantizer
// Round 9: single fp16 HMMA GEMM + top-2 prune + compensated-fp32 rescue
// (no fp64 in the hot path).
// outputs concatenated f32: out(33554432), loss(1), embed_idx(131072),
//   new_embed(262144), new_cluster_size(1024), new_ema_embed(262144)
// ---------------------------------------------------------------------------

#define NROWS   131072
#define KEMB    1024
#define DEMB    256
#define HWSZ    4096

#define LOSS_OFF 33554432
#define IDX_OFF  33554433
#define EMB_OFF  33685505
#define CS_OFF   33947649
#define EMA_OFF  33948673
#define FULL_OUT 34210817

#define SLOT_W  0.08f          // bs2 local rescue window

// scratch
__device__ __align__(16) int     g_idx[NROWS];
__device__ float   g_count[KEMB];
__device__ float   g_dw[DEMB * KEMB];
__device__ float   g_e2h[KEMB];
__device__ float   g_smooth[KEMB];
__device__ double  g_lossPart[256];
__device__ float   g_spill[262144];
__device__ __align__(16) __half  g_Ehf[KEMB * DEMB];  // E^T fp16, codes-major [k][d]
__device__ __align__(16) float   g_Etf[KEMB * DEMB];  // E^T fp32, codes-major [k][d]

__device__ __forceinline__ uint32_t smem_to_u32(const void* p) {
    uint32_t a;
    asm("{ .reg .u64 t; cvta.to.shared.u64 t, %1; cvt.u32.u64 %0, t; }"
        : "=r"(a) : "l"(p));
    return a;
}

#define LDSM4(r0, r1, r2, r3, a) \
    asm volatile("ldmatrix.sync.aligned.m8n8.x4.shared.b16 {%0,%1,%2,%3}, [%4];" \
                 : "=r"(r0), "=r"(r1), "=r"(r2), "=r"(r3) : "r"(a))
#define LDSM4T(r0, r1, r2, r3, a) \
    asm volatile("ldmatrix.sync.aligned.m8n8.x4.trans.shared.b16 {%0,%1,%2,%3}, [%4];" \
                 : "=r"(r0), "=r"(r1), "=r"(r2), "=r"(r3) : "r"(a))

#define MMA16816(c, a0, a1, a2, a3, b0, b1) \
    asm volatile("mma.sync.aligned.m16n8k16.row.col.f32.f16.f16.f32 " \
                 "{%0,%1,%2,%3}, {%4,%5,%6,%7}, {%8,%9}, {%0,%1,%2,%3};" \
                 : "+f"((c)[0]), "+f"((c)[1]), "+f"((c)[2]), "+f"((c)[3]) \
                 : "r"(a0), "r"(a1), "r"(a2), "r"(a3), "r"(b0), "r"(b1))

// ===========================================================================
// prep kernels (argmin stays launch index 3 for the ncu capture slot)
// ===========================================================================
__global__ void prep_zero_kernel() {
    int i = blockIdx.x * blockDim.x + threadIdx.x;
    if (i < DEMB * KEMB) g_dw[i] = 0.0f;
    if (i < KEMB) g_count[i] = 0.0f;
    if (i < 256) g_lossPart[i] = 0.0;
}

__global__ void prep_split_kernel(const float* __restrict__ embed) {
    int i = blockIdx.x * blockDim.x + threadIdx.x;   // 0..262143
    int k = i & (KEMB - 1);
    int d = i >> 10;
    float v = embed[i];                              // embed[d][k]
    g_Ehf[k * DEMB + d] = __float2half_rn(v);
    g_Etf[k * DEMB + d] = v;
}

__global__ void prep_norm_kernel(const float* __restrict__ embed) {
    int i = blockIdx.x * blockDim.x + threadIdx.x;   // 0..1023
    float s = 0.0f;
    #pragma unroll 4
    for (int d = 0; d < DEMB; d++) {
        float e = embed[d * KEMB + i];
        s = fmaf(e, e, s);
    }
    g_e2h[i] = 0.5f * s;
}

// ===========================================================================
// argmin: single fp16 HMMA GEMM + top-2 per slot + compensated fp32 rescue
//  CTA = 128 rows x 1024 codes, 256 threads (8 warps = 4m x 2n).
// ===========================================================================
#define PA 136                       // A pitch (m) in halfs
#define PB 72                        // B pitch (k) in halfs
#define SM_E2H  0                    // 1024 f32 = 4096 B
#define SM_CAND 4608                 // 128 u64 (packed winner)
#define SM_A    8192                 // Ah 256*136*2 = 69632
#define SM_ALO  (8192 + 69632)       // Al
#define SM_B    (8192 + 2 * 69632)   // 147456: 2 stages x 18432
#define SM_TOT  (SM_B + 2 * 18432)   // 184320

__device__ __forceinline__ void loadB(char* smem, int chunk, int tid) {
    const int stage = chunk & 1;
    const int nb = chunk >> 2, kc = chunk & 3;
    #pragma unroll
    for (int j = 0; j < 4; j++) {
        int i = tid + j * 256;           // 0..1023
        int r = i >> 3;                  // code row 0..127
        int c = i & 7;                   // 16B chunk along k
        const __half* src = g_Ehf + ((size_t)(nb * 128 + r) << 8) + kc * 64 + c * 8;
        uint4 v = *(const uint4*)src;
        *(uint4*)(smem + SM_B + stage * 18432 + r * (PB * 2) + c * 16) = v;
    }
}

// compensated fp32 rescore: dot(x_m, e_k) with TwoProd + TwoSum, no fp64
__device__ __forceinline__ void rescore(char* smem, unsigned long long* cand,
                                        const float* e2h, int m, int k) {
    const __half* Ah = (const __half*)(smem + SM_A);
    const __half* Al = (const __half*)(smem + SM_ALO);
    const float4* ev = (const float4*)(g_Etf + ((size_t)k << 8));
    float s[4] = {0.f, 0.f, 0.f, 0.f};
    float cc[4] = {0.f, 0.f, 0.f, 0.f};
    #pragma unroll 4
    for (int d4 = 0; d4 < 64; d4++) {
        float4 e4 = __ldg(&ev[d4]);
        const float ej[4] = {e4.x, e4.y, e4.z, e4.w};
        int d = d4 * 4;
        #pragma unroll
        for (int j = 0; j < 4; j++) {
            float xv = __half2float(Ah[(d + j) * PA + m])
                     + __half2float(Al[(d + j) * PA + m]);
            float p = xv * ej[j];
            float perr = fmaf(xv, ej[j], -p);
            float t = s[j] + p;               // TwoSum
            float bb = t - s[j];
            float err = (s[j] - (t - bb)) + (p - bb);
            s[j] = t;
            cc[j] += perr + err;
        }
    }
    float dot = ((s[0] + s[1]) + (s[2] + s[3])) + ((cc[0] + cc[1]) + (cc[2] + cc[3]));
    float sc = e2h[k] - dot;
    uint32_t u = __float_as_uint(sc);
    u = (u & 0x80000000u) ? ~u : (u | 0x80000000u);
    unsigned long long key = ((unsigned long long)u << 10) | (unsigned)k;
    atomicMin(&cand[m], key);
}

__global__ __launch_bounds__(256, 1)
void argmin_mma_kernel(const float* __restrict__ x, float* __restrict__ outIdxF) {
    extern __shared__ char smem[];
    const uint32_t sb = smem_to_u32(smem);
    const int tid = threadIdx.x, lane = tid & 31, wid = tid >> 5;
    const int wm = wid & 3, wn = wid >> 2;

    float* e2h = (float*)(smem + SM_E2H);
    unsigned long long* cand = (unsigned long long*)(smem + SM_CAND);
    for (int i = tid; i < KEMB; i += 256) e2h[i] = g_e2h[i];
    if (tid < 128) cand[tid] = 0xFFFFFFFFFFFFFFFFull;

    // stage A (x rows) as fp16 hi/lo, k-major [d][m], pitch PA
    const int n0 = blockIdx.x << 7;
    const float* xb = x + ((size_t)(n0 >> 12) << 20) + (n0 & (HWSZ - 1));
    __half* Ah = (__half*)(smem + SM_A);
    __half* Al = (__half*)(smem + SM_ALO);
    for (int i = tid; i < 32768; i += 256) {
        int d = i >> 7, m = i & 127;
        float v = xb[(size_t)d * HWSZ + m];
        __half h = __float2half_rn(v);
        float r = v - __half2float(h);
        Ah[d * PA + m] = h;
        Al[d * PA + m] = __float2half_rn(r);
    }
    loadB(smem, 0, tid);
    __syncthreads();

    // lane geometry
    const int g = lane >> 2, t = lane & 3;
    const uint32_t a_k = (uint32_t)((lane & 7) + ((lane & 16) ? 8 : 0));
    const uint32_t a_m = (uint32_t)((lane & 8) ? 8 : 0);
    const uint32_t b_n = (uint32_t)((lane & 7) + ((lane & 16) ? 8 : 0));
    const uint32_t b_k = (uint32_t)((lane & 8) ? 8 : 0);

    // top-2 per slot (4 slots: s = mt*2 + rowhalf)
    float bs1[4], bs2[4];
    int   bk1[4], bk2[4];
    #pragma unroll
    for (int s = 0; s < 4; s++) {
        bs1[s] = 3.4e38f; bs2[s] = 3.4e38f; bk1[s] = 0; bk2[s] = 0;
    }

    #pragma unroll 1
    for (int nb = 0; nb < 8; nb++) {
        float c[2][8][4];
        #pragma unroll
        for (int mt = 0; mt < 2; mt++)
            #pragma unroll
            for (int nt = 0; nt < 8; nt++)
                #pragma unroll
                for (int q = 0; q < 4; q++) c[mt][nt][q] = 0.0f;

        #pragma unroll 1
        for (int kc = 0; kc < 4; kc++) {
            const int chunk = nb * 4 + kc;
            if (chunk < 31) loadB(smem, chunk + 1, tid);
            const uint32_t bbase = sb + SM_B + (uint32_t)(chunk & 1) * 18432;

            #pragma unroll
            for (int ks = 0; ks < 4; ks++) {
                const uint32_t kA = (uint32_t)(kc * 64 + ks * 16);
                uint32_t ah[2][4];
                #pragma unroll
                for (int mt = 0; mt < 2; mt++) {
                    uint32_t aaddr = sb + SM_A
                        + ((kA + a_k) * PA + (uint32_t)(wm * 32 + mt * 16) + a_m) * 2;
                    LDSM4T(ah[mt][0], ah[mt][1], ah[mt][2], ah[mt][3], aaddr);
                }
                uint32_t bh[4][4];
                #pragma unroll
                for (int p = 0; p < 4; p++) {
                    uint32_t baddr = bbase
                        + (((uint32_t)(wn * 64 + p * 16) + b_n) * PB
                           + (uint32_t)(ks * 16) + b_k) * 2;
                    LDSM4(bh[p][0], bh[p][1], bh[p][2], bh[p][3], baddr);
                }
                #pragma unroll
                for (int p = 0; p < 4; p++) {
                    #pragma unroll
                    for (int mt = 0; mt < 2; mt++) {
                        MMA16816(c[mt][2 * p],     ah[mt][0], ah[mt][1], ah[mt][2], ah[mt][3], bh[p][0], bh[p][1]);
                        MMA16816(c[mt][2 * p + 1], ah[mt][0], ah[mt][1], ah[mt][2], ah[mt][3], bh[p][2], bh[p][3]);
                    }
                }
            }
            __syncthreads();
        }

        // epilogue: top-2 update, ascending k (strict < keeps first-min)
        #pragma unroll
        for (int mt = 0; mt < 2; mt++) {
            #pragma unroll
            for (int nt = 0; nt < 8; nt++) {
                int n = nb * 128 + wn * 64 + nt * 8 + 2 * t;
                float sA0 = e2h[n]     - c[mt][nt][0];
                float sA1 = e2h[n + 1] - c[mt][nt][1];
                float sB0 = e2h[n]     - c[mt][nt][2];
                float sB1 = e2h[n + 1] - c[mt][nt][3];
                int s = mt * 2;
                if (sA0 < bs1[s]) { bs2[s]=bs1[s]; bk2[s]=bk1[s]; bs1[s]=sA0; bk1[s]=n; }
                else if (sA0 < bs2[s]) { bs2[s]=sA0; bk2[s]=n; }
                if (sA1 < bs1[s]) { bs2[s]=bs1[s]; bk2[s]=bk1[s]; bs1[s]=sA1; bk1[s]=n+1; }
                else if (sA1 < bs2[s]) { bs2[s]=sA1; bk2[s]=n+1; }
                s++;
                if (sB0 < bs1[s]) { bs2[s]=bs1[s]; bk2[s]=bk1[s]; bs1[s]=sB0; bk1[s]=n; }
                else if (sB0 < bs2[s]) { bs2[s]=sB0; bk2[s]=n; }
                if (sB1 < bs1[s]) { bs2[s]=bs1[s]; bk2[s]=bk1[s]; bs1[s]=sB1; bk1[s]=n+1; }
                else if (sB1 < bs2[s]) { bs2[s]=sB1; bk2[s]=n+1; }
            }
        }
    }
    __syncthreads();   // all GEMM smem traffic done; cand/Ah/Al stable

    // rescue: rescore every slot's bs1 (always) + bs2 when locally close
    #pragma unroll
    for (int s = 0; s < 4; s++) {
        int row = wm * 32 + (s >> 1) * 16 + (s & 1) * 8 + g;
        rescore(smem, cand, e2h, row, bk1[s]);
        if (bs2[s] < bs1[s] + SLOT_W) rescore(smem, cand, e2h, row, bk2[s]);
    }
    __syncthreads();

    if (tid < 128) {
        int k = (int)(cand[tid] & 1023u);
        int n = n0 + tid;
        g_idx[n] = k;
        outIdxF[n] = (float)k;
        atomicAdd(&g_count[k], 1.0f);
    }
}

// ===========================================================================
// writeback: out = gather(embed, idx), loss partials, dw scatter
//  grid 8192 CTAs: one per (b, d); embed row cached in smem; 4 chunks.
// ===========================================================================
__global__ __launch_bounds__(256)
void writeback_kernel(const float* __restrict__ x,
                      const float* __restrict__ embed,
                      float* __restrict__ out) {
    __shared__ float erow[KEMB];
    __shared__ float wsum[8];
    const int bid = blockIdx.x;            // 0..8191
    const int b = bid >> 8, d = bid & 255;
    const int tid = threadIdx.x;

    *(float4*)&erow[tid * 4] = *(const float4*)(embed + ((size_t)d << 10) + tid * 4);
    __syncthreads();

    const size_t base = ((size_t)b << 20) + ((size_t)d << 12);
    const int n0 = b << 12;
    float* dwrow = g_dw + ((size_t)d << 10);
    float ls = 0.0f;

    #pragma unroll
    for (int c2 = 0; c2 < 4; c2++) {
        const int hw = c2 * 1024 + tid * 4;
        float4 xv = *(const float4*)(x + base + hw);
        int4   kv = *(const int4*)(g_idx + n0 + hw);
        float q0 = erow[kv.x], q1 = erow[kv.y], q2 = erow[kv.z], q3 = erow[kv.w];
        *(float4*)(out + base + hw) = make_float4(q0, q1, q2, q3);

        float d0 = q0 - xv.x, d1 = q1 - xv.y, d2 = q2 - xv.z, d3 = q3 - xv.w;
        ls += d0 * d0 + d1 * d1 + d2 * d2 + d3 * d3;

        atomicAdd(dwrow + kv.x, xv.x);
        atomicAdd(dwrow + kv.y, xv.y);
        atomicAdd(dwrow + kv.z, xv.z);
        atomicAdd(dwrow + kv.w, xv.w);
    }

    #pragma unroll
    for (int off = 16; off; off >>= 1)
        ls += __shfl_xor_sync(0xffffffffu, ls, off);
    int lane = tid & 31, w = tid >> 5;
    if (lane == 0) wsum[w] = ls;
    __syncthreads();
    if (tid == 0) {
        float bsum = 0.0f;
        #pragma unroll
        for (int i = 0; i < 8; i++) bsum += wsum[i];
        atomicAdd(&g_lossPart[bid & 255], (double)bsum);
    }
}

// ===========================================================================
// cluster-size / smoothing / loss finalize (shuffle-based)
// ===========================================================================
__global__ __launch_bounds__(1024)
void cs_kernel(const float* __restrict__ cs_in,
               float* __restrict__ outCS,
               float* __restrict__ outLoss) {
    __shared__ float wred[32];
    __shared__ double lred[8];
    __shared__ float nsum_s;
    int k = threadIdx.x;
    int lane = k & 31, w = k >> 5;

    float ncs = cs_in[k] * 0.9f + 0.1f * g_count[k];
    outCS[k] = ncs;
    float sum = ncs;
    #pragma unroll
    for (int off = 16; off; off >>= 1)
        sum += __shfl_xor_sync(0xffffffffu, sum, off);
    if (lane == 0) wred[w] = sum;

    if (k < 256) {
        double lp = g_lossPart[k];
        #pragma unroll
        for (int off = 16; off; off >>= 1)
            lp += __shfl_xor_sync(0xffffffffu, lp, off);
        if (lane == 0) lred[w] = lp;
    }
    __syncthreads();
    if (w == 0) {
        float v = wred[lane];
        #pragma unroll
        for (int off = 16; off; off >>= 1)
            v += __shfl_xor_sync(0xffffffffu, v, off);
        if (lane == 0) nsum_s = v;
    }
    __syncthreads();
    float nsum = nsum_s;
    g_smooth[k] = nsum * ((ncs + 1e-5f) / (nsum + ncs * 1e-5f));
    if (k == 0) {
        double ls = lred[0] + lred[1] + lred[2] + lred[3]
                  + lred[4] + lred[5] + lred[6] + lred[7];
        outLoss[0] = (float)(0.25 * ls / 33554432.0);
    }
}

__global__ __launch_bounds__(256)
void emb_kernel(const float* __restrict__ ema_in,
                float* __restrict__ outEmb,
                float* __restrict__ outEma) {
    int i = blockIdx.x * blockDim.x + threadIdx.x;
    int k = i & 1023;
    float nema = ema_in[i] * 0.9f + 0.1f * g_dw[i];
    outEma[i] = nema;
    outEmb[i] = nema / g_smooth[k];
}

// ===========================================================================
extern "C" void kernel_launch(void* const* d_in, const int* in_sizes, int n_in,
                              void* d_out, int out_size) {
    const float* x     = (const float*)d_in[0];
    const float* embed = (const float*)d_in[1];
    const float* cs    = (const float*)d_in[2];
    const float* ema   = (const float*)d_in[3];
    float* out = (float*)d_out;

    float* spill = nullptr;
    cudaGetSymbolAddress((void**)&spill, g_spill);

    const bool full = (out_size >= FULL_OUT);
    float* pIdx  = full ? out + IDX_OFF  : spill;
    float* pLoss = full ? out + LOSS_OFF : spill;
    float* pEmb  = full ? out + EMB_OFF  : spill;
    float* pCS   = full ? out + CS_OFF   : spill;
    float* pEma  = full ? out + EMA_OFF  : spill;

    cudaFuncSetAttribute(argmin_mma_kernel,
                         cudaFuncAttributeMaxDynamicSharedMemorySize, SM_TOT);

    prep_zero_kernel<<<1024, 256>>>();
    prep_split_kernel<<<1024, 256>>>(embed);
    prep_norm_kernel<<<4, 256>>>(embed);
    argmin_mma_kernel<<<NROWS / 128, 256, SM_TOT>>>(x, pIdx);   // index 3
    writeback_kernel<<<8192, 256>>>(x, embed, out);
    cs_kernel<<<1, 1024>>>(cs, pCS, pLoss);
    emb_kernel<<<1024, 256>>>(ema, pEmb, pEma);
}

// round 14
// speedup vs baseline: 2.6718x; 1.9156x over previous
#include <cuda_runtime.h>
#include <cuda_fp16.h>
#include <cstdint>

// ---------------------------------------------------------------------------
// FeatureQuantizerEMA — VQ-VAE EMA quantizer
// Round 11: single fp16 HMMA GEMM + per-half top-2 prune + cooperative
// warp-level exact-ish (TwoProd+Kahan fp32) rescue. No fp64, no serial LDS.
// outputs concatenated f32: out(33554432), loss(1), embed_idx(131072),
//   new_embed(262144), new_cluster_size(1024), new_ema_embed(262144)
// ---------------------------------------------------------------------------

#define NROWS   131072
#define KEMB    1024
#define DEMB    256
#define HWSZ    4096

#define LOSS_OFF 33554432
#define IDX_OFF  33554433
#define EMB_OFF  33685505
#define CS_OFF   33947649
#define EMA_OFF  33948673
#define FULL_OUT 34210817

// scratch
__device__ __align__(16) int     g_idx[NROWS];
__device__ float   g_count[KEMB];
__device__ float   g_dw[DEMB * KEMB];
__device__ float   g_e2h[KEMB];
__device__ float   g_smooth[KEMB];
__device__ double  g_lossPart[256];
__device__ float   g_spill[262144];
__device__ __align__(16) __half  g_Ehf[KEMB * DEMB];  // E^T fp16, codes-major [k][d]
__device__ __align__(16) float   g_Etf[KEMB * DEMB];  // E^T fp32, codes-major [k][d]

__device__ __forceinline__ uint32_t smem_to_u32(const void* p) {
    uint32_t a;
    asm("{ .reg .u64 t; cvta.to.shared.u64 t, %1; cvt.u32.u64 %0, t; }"
        : "=r"(a) : "l"(p));
    return a;
}

#define LDSM4(r0, r1, r2, r3, a) \
    asm volatile("ldmatrix.sync.aligned.m8n8.x4.shared.b16 {%0,%1,%2,%3}, [%4];" \
                 : "=r"(r0), "=r"(r1), "=r"(r2), "=r"(r3) : "r"(a))
#define LDSM4T(r0, r1, r2, r3, a) \
    asm volatile("ldmatrix.sync.aligned.m8n8.x4.trans.shared.b16 {%0,%1,%2,%3}, [%4];" \
                 : "=r"(r0), "=r"(r1), "=r"(r2), "=r"(r3) : "r"(a))

#define MMA16816(c, a0, a1, a2, a3, b0, b1) \
    asm volatile("mma.sync.aligned.m16n8k16.row.col.f32.f16.f16.f32 " \
                 "{%0,%1,%2,%3}, {%4,%5,%6,%7}, {%8,%9}, {%0,%1,%2,%3};" \
                 : "+f"((c)[0]), "+f"((c)[1]), "+f"((c)[2]), "+f"((c)[3]) \
                 : "r"(a0), "r"(a1), "r"(a2), "r"(a3), "r"(b0), "r"(b1))

// monotonic float->uint map: preserves < order, packs with index for tie-break
__device__ __forceinline__ unsigned long long packKey(float s, int k) {
    uint32_t u = __float_as_uint(s);
    u = (u & 0x80000000u) ? ~u : (u | 0x80000000u);
    return ((unsigned long long)u << 32) | (unsigned)k;
}

// ===========================================================================
// prep kernels (argmin stays launch index 3 for the ncu capture slot)
// ===========================================================================
__global__ void prep_zero_kernel() {
    int i = blockIdx.x * blockDim.x + threadIdx.x;
    if (i < DEMB * KEMB) g_dw[i] = 0.0f;
    if (i < KEMB) g_count[i] = 0.0f;
    if (i < 256) g_lossPart[i] = 0.0;
}

__global__ void prep_split_kernel(const float* __restrict__ embed) {
    int i = blockIdx.x * blockDim.x + threadIdx.x;   // 0..262143
    int k = i & (KEMB - 1);
    int d = i >> 10;
    float v = embed[i];                              // embed[d][k]
    g_Ehf[k * DEMB + d] = __float2half_rn(v);
    g_Etf[k * DEMB + d] = v;
}

__global__ void prep_norm_kernel(const float* __restrict__ embed) {
    int i = blockIdx.x * blockDim.x + threadIdx.x;   // 0..1023
    float s = 0.0f;
    #pragma unroll 4
    for (int d = 0; d < DEMB; d++) {
        float e = embed[d * KEMB + i];
        s = fmaf(e, e, s);
    }
    g_e2h[i] = 0.5f * s;
}

// ===========================================================================
// argmin: single fp16 HMMA GEMM + top-2 per slot + cooperative rescue
//  CTA = 128 rows x 1024 codes, 256 threads (8 warps = 4m x 2n).
// ===========================================================================
#define PA 136                       // A pitch (m) in halfs
#define PB 72                        // B pitch (k) in halfs
#define SM_E2H  0                    // 1024 f32 = 4096 B
#define SM_CAND 4608                 // int candK[128][4] = 2048 B
#define SM_A    8192                 // Ah 256*136*2 = 69632
#define SM_ALO  (8192 + 69632)       // Al
#define SM_B    (8192 + 2 * 69632)   // 147456: 2 stages x 18432
#define SM_TOT  (SM_B + 2 * 18432)   // 184320

__device__ __forceinline__ void loadB(char* smem, int chunk, int tid) {
    const int stage = chunk & 1;
    const int nb = chunk >> 2, kc = chunk & 3;
    #pragma unroll
    for (int j = 0; j < 4; j++) {
        int i = tid + j * 256;           // 0..1023
        int r = i >> 3;                  // code row 0..127
        int c = i & 7;                   // 16B chunk along k
        const __half* src = g_Ehf + ((size_t)(nb * 128 + r) << 8) + kc * 64 + c * 8;
        uint4 v = *(const uint4*)src;
        *(uint4*)(smem + SM_B + stage * 18432 + r * (PB * 2) + c * 16) = v;
    }
}

__global__ __launch_bounds__(256, 1)
void argmin_mma_kernel(const float* __restrict__ x, float* __restrict__ outIdxF) {
    extern __shared__ char smem[];
    const uint32_t sb = smem_to_u32(smem);
    const int tid = threadIdx.x, lane = tid & 31, wid = tid >> 5;
    const int wm = wid & 3, wn = wid >> 2;

    float* e2h = (float*)(smem + SM_E2H);
    int* candK = (int*)(smem + SM_CAND);     // [128][4]
    for (int i = tid; i < KEMB; i += 256) e2h[i] = g_e2h[i];

    // stage A (x rows) as fp16 hi/lo, k-major [d][m], pitch PA
    const int n0 = blockIdx.x << 7;
    const float* xb = x + ((size_t)(n0 >> 12) << 20) + (n0 & (HWSZ - 1));
    __half* Ah = (__half*)(smem + SM_A);
    __half* Al = (__half*)(smem + SM_ALO);
    for (int i = tid; i < 32768; i += 256) {
        int d = i >> 7, m = i & 127;
        float v = xb[(size_t)d * HWSZ + m];
        __half h = __float2half_rn(v);
        float r = v - __half2float(h);
        Ah[d * PA + m] = h;
        Al[d * PA + m] = __float2half_rn(r);
    }
    loadB(smem, 0, tid);
    __syncthreads();

    // lane geometry
    const int g = lane >> 2, t = lane & 3;
    const uint32_t a_k = (uint32_t)((lane & 7) + ((lane & 16) ? 8 : 0));
    const uint32_t a_m = (uint32_t)((lane & 8) ? 8 : 0);
    const uint32_t b_n = (uint32_t)((lane & 7) + ((lane & 16) ? 8 : 0));
    const uint32_t b_k = (uint32_t)((lane & 8) ? 8 : 0);

    // top-2 per slot (4 slots: s = mt*2 + rowhalf)
    float bs1[4], bs2[4];
    int   bk1[4], bk2[4];
    #pragma unroll
    for (int s = 0; s < 4; s++) {
        bs1[s] = 3.4e38f; bs2[s] = 3.4e38f; bk1[s] = 0; bk2[s] = 0;
    }

    #pragma unroll 1
    for (int nb = 0; nb < 8; nb++) {
        float c[2][8][4];
        #pragma unroll
        for (int mt = 0; mt < 2; mt++)
            #pragma unroll
            for (int nt = 0; nt < 8; nt++)
                #pragma unroll
                for (int q = 0; q < 4; q++) c[mt][nt][q] = 0.0f;

        #pragma unroll 1
        for (int kc = 0; kc < 4; kc++) {
            const int chunk = nb * 4 + kc;
            if (chunk < 31) loadB(smem, chunk + 1, tid);
            const uint32_t bbase = sb + SM_B + (uint32_t)(chunk & 1) * 18432;

            #pragma unroll
            for (int ks = 0; ks < 4; ks++) {
                const uint32_t kA = (uint32_t)(kc * 64 + ks * 16);
                uint32_t ah[2][4];
                #pragma unroll
                for (int mt = 0; mt < 2; mt++) {
                    uint32_t aaddr = sb + SM_A
                        + ((kA + a_k) * PA + (uint32_t)(wm * 32 + mt * 16) + a_m) * 2;
                    LDSM4T(ah[mt][0], ah[mt][1], ah[mt][2], ah[mt][3], aaddr);
                }
                uint32_t bh[4][4];
                #pragma unroll
                for (int p = 0; p < 4; p++) {
                    uint32_t baddr = bbase
                        + (((uint32_t)(wn * 64 + p * 16) + b_n) * PB
                           + (uint32_t)(ks * 16) + b_k) * 2;
                    LDSM4(bh[p][0], bh[p][1], bh[p][2], bh[p][3], baddr);
                }
                #pragma unroll
                for (int p = 0; p < 4; p++) {
                    #pragma unroll
                    for (int mt = 0; mt < 2; mt++) {
                        MMA16816(c[mt][2 * p],     ah[mt][0], ah[mt][1], ah[mt][2], ah[mt][3], bh[p][0], bh[p][1]);
                        MMA16816(c[mt][2 * p + 1], ah[mt][0], ah[mt][1], ah[mt][2], ah[mt][3], bh[p][2], bh[p][3]);
                    }
                }
            }
            __syncthreads();
        }

        // epilogue: top-2 update, ascending k (strict < keeps first-min)
        #pragma unroll
        for (int mt = 0; mt < 2; mt++) {
            #pragma unroll
            for (int nt = 0; nt < 8; nt++) {
                int n = nb * 128 + wn * 64 + nt * 8 + 2 * t;
                float sA0 = e2h[n]     - c[mt][nt][0];
                float sA1 = e2h[n + 1] - c[mt][nt][1];
                float sB0 = e2h[n]     - c[mt][nt][2];
                float sB1 = e2h[n + 1] - c[mt][nt][3];
                int s = mt * 2;
                if (sA0 < bs1[s]) { bs2[s]=bs1[s]; bk2[s]=bk1[s]; bs1[s]=sA0; bk1[s]=n; }
                else if (sA0 < bs2[s]) { bs2[s]=sA0; bk2[s]=n; }
                if (sA1 < bs1[s]) { bs2[s]=bs1[s]; bk2[s]=bk1[s]; bs1[s]=sA1; bk1[s]=n+1; }
                else if (sA1 < bs2[s]) { bs2[s]=sA1; bk2[s]=n+1; }
                s++;
                if (sB0 < bs1[s]) { bs2[s]=bs1[s]; bk2[s]=bk1[s]; bs1[s]=sB0; bk1[s]=n; }
                else if (sB0 < bs2[s]) { bs2[s]=sB0; bk2[s]=n; }
                if (sB1 < bs1[s]) { bs2[s]=bs1[s]; bk2[s]=bk1[s]; bs1[s]=sB1; bk1[s]=n+1; }
                else if (sB1 < bs2[s]) { bs2[s]=sB1; bk2[s]=n+1; }
            }
        }
    }

    // t-lane merge: per slot, merge 4 sorted top-2 pairs -> half top-2
    #pragma unroll
    for (int s = 0; s < 4; s++) {
        unsigned long long k1 = packKey(bs1[s], bk1[s]);
        unsigned long long k2 = packKey(bs2[s], bk2[s]);
        #pragma unroll
        for (int off = 1; off <= 2; off <<= 1) {
            unsigned long long o1 = __shfl_xor_sync(0xffffffffu, k1, off);
            unsigned long long o2 = __shfl_xor_sync(0xffffffffu, k2, off);
            unsigned long long lo = (k1 < o1) ? k1 : o1;
            unsigned long long hi = (k1 < o1) ? o1 : k1;
            unsigned long long m2 = (k2 < o2) ? k2 : o2;
            k1 = lo;
            k2 = (hi < m2) ? hi : m2;
        }
        if (t == 0) {
            int row = wm * 32 + (s >> 1) * 16 + (s & 1) * 8 + g;
            candK[row * 4 + wn * 2 + 0] = (int)(k1 & 1023u);
            candK[row * 4 + wn * 2 + 1] = (int)(k2 & 1023u);
        }
    }
    __syncthreads();

    // cooperative rescue: warp wid handles rows wid*16..wid*16+15.
    // lane = 8*c + e: candidate c (0..3), element group e; lane e covers
    // d = e + 8*i  (conflict-free LDS: bank stride 4e, c-groups broadcast).
    {
        const int cslot = lane >> 3, e = lane & 7;
        for (int j = 0; j < 16; j++) {
            const int row = wid * 16 + j;
            const int k = candK[row * 4 + cslot];
            const float* ek = g_Etf + ((size_t)k << 8);
            float sum = 0.0f, comp = 0.0f;
            #pragma unroll 8
            for (int i = 0; i < 32; i++) {
                int d = e + 8 * i;
                float xv = __half2float(Ah[d * PA + row])
                         + __half2float(Al[d * PA + row]);
                float ev = __ldg(ek + d);
                float p  = xv * ev;
                float pe = fmaf(xv, ev, -p);       // exact product tail
                comp -= pe;
                float y = p - comp;
                float tt = sum + y;
                comp = (tt - sum) - y;
                sum = tt;
            }
            sum -= comp;
            // reduce over the 8 lanes of this candidate group
            sum += __shfl_down_sync(0xffffffffu, sum, 4);
            sum += __shfl_down_sync(0xffffffffu, sum, 2);
            sum += __shfl_down_sync(0xffffffffu, sum, 1);
            unsigned long long key = packKey(e2h[k] - sum, k);
            // min across the 4 candidate groups (lanes 0,8,16,24 valid)
            unsigned long long o = __shfl_xor_sync(0xffffffffu, key, 8);
            key = (key < o) ? key : o;
            o = __shfl_xor_sync(0xffffffffu, key, 16);
            key = (key < o) ? key : o;
            if (lane == 0) {
                int kb = (int)(key & 1023u);
                int n = n0 + row;
                g_idx[n] = kb;
                outIdxF[n] = (float)kb;
                atomicAdd(&g_count[kb], 1.0f);
            }
        }
    }
}

// ===========================================================================
// writeback: out = gather(embed, idx), loss partials, dw scatter
//  grid 8192 CTAs: one per (b, d); embed row cached in smem; 4 chunks.
// ===========================================================================
__global__ __launch_bounds__(256)
void writeback_kernel(const float* __restrict__ x,
                      const float* __restrict__ embed,
                      float* __restrict__ out) {
    __shared__ float erow[KEMB];
    __shared__ float wsum[8];
    const int bid = blockIdx.x;            // 0..8191
    const int b = bid >> 8, d = bid & 255;
    const int tid = threadIdx.x;

    *(float4*)&erow[tid * 4] = *(const float4*)(embed + ((size_t)d << 10) + tid * 4);
    __syncthreads();

    const size_t base = ((size_t)b << 20) + ((size_t)d << 12);
    const int n0 = b << 12;
    float* dwrow = g_dw + ((size_t)d << 10);
    float ls = 0.0f;

    #pragma unroll
    for (int c2 = 0; c2 < 4; c2++) {
        const int hw = c2 * 1024 + tid * 4;
        float4 xv = *(const float4*)(x + base + hw);
        int4   kv = *(const int4*)(g_idx + n0 + hw);
        float q0 = erow[kv.x], q1 = erow[kv.y], q2 = erow[kv.z], q3 = erow[kv.w];
        *(float4*)(out + base + hw) = make_float4(q0, q1, q2, q3);

        float d0 = q0 - xv.x, d1 = q1 - xv.y, d2 = q2 - xv.z, d3 = q3 - xv.w;
        ls += d0 * d0 + d1 * d1 + d2 * d2 + d3 * d3;

        atomicAdd(dwrow + kv.x, xv.x);
        atomicAdd(dwrow + kv.y, xv.y);
        atomicAdd(dwrow + kv.z, xv.z);
        atomicAdd(dwrow + kv.w, xv.w);
    }

    #pragma unroll
    for (int off = 16; off; off >>= 1)
        ls += __shfl_xor_sync(0xffffffffu, ls, off);
    int lane = tid & 31, w = tid >> 5;
    if (lane == 0) wsum[w] = ls;
    __syncthreads();
    if (tid == 0) {
        float bsum = 0.0f;
        #pragma unroll
        for (int i = 0; i < 8; i++) bsum += wsum[i];
        atomicAdd(&g_lossPart[bid & 255], (double)bsum);
    }
}

// ===========================================================================
// cluster-size / smoothing / loss finalize (shuffle-based)
// ===========================================================================
__global__ __launch_bounds__(1024)
void cs_kernel(const float* __restrict__ cs_in,
               float* __restrict__ outCS,
               float* __restrict__ outLoss) {
    __shared__ float wred[32];
    __shared__ double lred[8];
    __shared__ float nsum_s;
    int k = threadIdx.x;
    int lane = k & 31, w = k >> 5;

    float ncs = cs_in[k] * 0.9f + 0.1f * g_count[k];
    outCS[k] = ncs;
    float sum = ncs;
    #pragma unroll
    for (int off = 16; off; off >>= 1)
        sum += __shfl_xor_sync(0xffffffffu, sum, off);
    if (lane == 0) wred[w] = sum;

    if (k < 256) {
        double lp = g_lossPart[k];
        #pragma unroll
        for (int off = 16; off; off >>= 1)
            lp += __shfl_xor_sync(0xffffffffu, lp, off);
        if (lane == 0) lred[w] = lp;
    }
    __syncthreads();
    if (w == 0) {
        float v = wred[lane];
        #pragma unroll
        for (int off = 16; off; off >>= 1)
            v += __shfl_xor_sync(0xffffffffu, v, off);
        if (lane == 0) nsum_s = v;
    }
    __syncthreads();
    float nsum = nsum_s;
    g_smooth[k] = nsum * ((ncs + 1e-5f) / (nsum + ncs * 1e-5f));
    if (k == 0) {
        double ls = lred[0] + lred[1] + lred[2] + lred[3]
                  + lred[4] + lred[5] + lred[6] + lred[7];
        outLoss[0] = (float)(0.25 * ls / 33554432.0);
    }
}

__global__ __launch_bounds__(256)
void emb_kernel(const float* __restrict__ ema_in,
                float* __restrict__ outEmb,
                float* __restrict__ outEma) {
    int i = blockIdx.x * blockDim.x + threadIdx.x;
    int k = i & 1023;
    float nema = ema_in[i] * 0.9f + 0.1f * g_dw[i];
    outEma[i] = nema;
    outEmb[i] = nema / g_smooth[k];
}

// ===========================================================================
extern "C" void kernel_launch(void* const* d_in, const int* in_sizes, int n_in,
                              void* d_out, int out_size) {
    const float* x     = (const float*)d_in[0];
    const float* embed = (const float*)d_in[1];
    const float* cs    = (const float*)d_in[2];
    const float* ema   = (const float*)d_in[3];
    float* out = (float*)d_out;

    float* spill = nullptr;
    cudaGetSymbolAddress((void**)&spill, g_spill);

    const bool full = (out_size >= FULL_OUT);
    float* pIdx  = full ? out + IDX_OFF  : spill;
    float* pLoss = full ? out + LOSS_OFF : spill;
    float* pEmb  = full ? out + EMB_OFF  : spill;
    float* pCS   = full ? out + CS_OFF   : spill;
    float* pEma  = full ? out + EMA_OFF  : spill;

    cudaFuncSetAttribute(argmin_mma_kernel,
                         cudaFuncAttributeMaxDynamicSharedMemorySize, SM_TOT);

    prep_zero_kernel<<<1024, 256>>>();
    prep_split_kernel<<<1024, 256>>>(embed);
    prep_norm_kernel<<<4, 256>>>(embed);
    argmin_mma_kernel<<<NROWS / 128, 256, SM_TOT>>>(x, pIdx);   // index 3
    writeback_kernel<<<8192, 256>>>(x, embed, out);
    cs_kernel<<<1, 1024>>>(cs, pCS, pLoss);
    emb_kernel<<<1024, 256>>>(ema, pEmb, pEma);
}